// round 1
// baseline (speedup 1.0000x reference)
#include <cuda_runtime.h>
#include <cuda_bf16.h>
#include <math.h>

// Model dims
#define NL 32
#define D  256
#define DI 512
#define NS 16      // d_state
#define RR 16      // dt_rank
#define KC 4       // d_conv
#define VV 4096
#define FF 1024
#define BB 32
#define LL 256
#define TT (BB*LL)   // 8192 tokens

// ---------------- scratch (static device globals; no allocation allowed) ----
__device__ float g_x  [TT * D];        // residual stream
__device__ float g_h  [TT * D];        // LN output
__device__ float g_xz [TT * 2 * DI];   // in_proj output
__device__ float g_xc [TT * DI];       // conv+silu output
__device__ float g_dbc[TT * 48];       // x_proj output (R + 2N = 48)
__device__ float g_dt [TT * DI];       // softplus dt
__device__ float g_y  [TT * DI];       // scan output (gated)
__device__ float g_h1 [TT * FF];       // MLP hidden

// ---------------- embedding --------------------------------------------------
__global__ void embed_kernel(const int* __restrict__ tok,
                             const float* __restrict__ emb,
                             float* __restrict__ x)
{
    int t = blockIdx.x, d = threadIdx.x;
    x[t * D + d] = emb[(size_t)tok[t] * D + d];
}

// ---------------- layernorm --------------------------------------------------
__global__ void ln_kernel(const float* __restrict__ x,
                          const float* __restrict__ w,
                          const float* __restrict__ b,
                          float* __restrict__ h)
{
    int t = blockIdx.x, d = threadIdx.x;
    float v = x[t * D + d];
    float s = v, s2 = v * v;
    #pragma unroll
    for (int o = 16; o > 0; o >>= 1) {
        s  += __shfl_xor_sync(0xffffffffu, s,  o);
        s2 += __shfl_xor_sync(0xffffffffu, s2, o);
    }
    __shared__ float ws[8], ws2[8];
    int wi = d >> 5;
    if ((d & 31) == 0) { ws[wi] = s; ws2[wi] = s2; }
    __syncthreads();
    if (d < 32) {
        float a  = (d < 8) ? ws[d]  : 0.f;
        float a2 = (d < 8) ? ws2[d] : 0.f;
        #pragma unroll
        for (int o = 4; o > 0; o >>= 1) {
            a  += __shfl_xor_sync(0xffffffffu, a,  o);
            a2 += __shfl_xor_sync(0xffffffffu, a2, o);
        }
        if (d == 0) { ws[0] = a; ws2[0] = a2; }
    }
    __syncthreads();
    float mu  = ws[0] * (1.f / D);
    float var = ws2[0] * (1.f / D) - mu * mu;
    float inv = rsqrtf(var + 1e-5f);
    h[t * D + d] = (v - mu) * inv * w[d] + b[d];
}

// ---------------- generic NT GEMM: C[m][n] = dot(A[m,:], B[n,:]) + epilogue --
// A: M x K (lda), B: N x K (ldb), C: M x ldc
// EPI: 0 plain, 1 bias+relu, 2 bias, 3 residual add, 4 bias+softplus
#define BM 128
#define BN 64
#define BKK 16

template<int EPI>
__global__ __launch_bounds__(256)
void gemm_nt(const float* __restrict__ A, int lda,
             const float* __restrict__ B, int ldb,
             float* __restrict__ C, int ldc,
             const float* __restrict__ bias,
             const float* __restrict__ res,
             int M, int N, int K)
{
    __shared__ float As[BM][BKK];       // m-major
    __shared__ float Bs[BKK][BN];       // k-major
    int tid = threadIdx.x;
    int bm = blockIdx.y * BM, bn = blockIdx.x * BN;
    int tx = tid & 15, ty = tid >> 4;
    int m0 = ty * 8, n0 = tx * 4;
    float acc[8][4];
    #pragma unroll
    for (int i = 0; i < 8; i++)
        #pragma unroll
        for (int j = 0; j < 4; j++) acc[i][j] = 0.f;

    for (int k0 = 0; k0 < K; k0 += BKK) {
        // A tile: 128x16 = 512 float4, 2 per thread
        #pragma unroll
        for (int it = 0; it < 2; it++) {
            int idx = tid + it * 256;
            int r = idx >> 2, c4 = idx & 3;
            float4 v = *reinterpret_cast<const float4*>(
                A + (size_t)(bm + r) * lda + k0 + c4 * 4);
            *reinterpret_cast<float4*>(&As[r][c4 * 4]) = v;
        }
        // B tile: 64x16 = 256 float4, 1 per thread (guard N)
        {
            int r = tid >> 2, c4 = tid & 3;
            float4 v = make_float4(0.f, 0.f, 0.f, 0.f);
            if (bn + r < N)
                v = *reinterpret_cast<const float4*>(
                    B + (size_t)(bn + r) * ldb + k0 + c4 * 4);
            Bs[c4 * 4 + 0][r] = v.x;
            Bs[c4 * 4 + 1][r] = v.y;
            Bs[c4 * 4 + 2][r] = v.z;
            Bs[c4 * 4 + 3][r] = v.w;
        }
        __syncthreads();
        #pragma unroll
        for (int k = 0; k < BKK; k++) {
            float ra[8];
            #pragma unroll
            for (int i = 0; i < 8; i++) ra[i] = As[m0 + i][k];
            float4 b4 = *reinterpret_cast<const float4*>(&Bs[k][n0]);
            float rb[4] = {b4.x, b4.y, b4.z, b4.w};
            #pragma unroll
            for (int i = 0; i < 8; i++)
                #pragma unroll
                for (int j = 0; j < 4; j++)
                    acc[i][j] = fmaf(ra[i], rb[j], acc[i][j]);
        }
        __syncthreads();
    }

    bool full = (bn + BN <= N);
    #pragma unroll
    for (int i = 0; i < 8; i++) {
        int m = bm + m0 + i;
        size_t base = (size_t)m * ldc + bn + n0;
        float v[4];
        #pragma unroll
        for (int j = 0; j < 4; j++) {
            int n = bn + n0 + j;
            float a = acc[i][j];
            if (EPI == 1) { a += bias[n]; a = fmaxf(a, 0.f); }
            else if (EPI == 2) { a += bias[n]; }
            else if (EPI == 3) { a += res[base + j]; }
            else if (EPI == 4) {
                a += bias[n];
                a = (a > 20.f) ? a : log1pf(expf(a));
            }
            v[j] = a;
        }
        if (full) {
            float4 o = make_float4(v[0], v[1], v[2], v[3]);
            *reinterpret_cast<float4*>(C + base) = o;
        } else {
            #pragma unroll
            for (int j = 0; j < 4; j++)
                if (bn + n0 + j < N) C[base + j] = v[j];
        }
    }
}

// ---------------- causal depthwise conv1d + SiLU ----------------------------
__global__ void conv_kernel(const float* __restrict__ xz,
                            const float* __restrict__ cw,
                            const float* __restrict__ cb,
                            float* __restrict__ xc)
{
    int t = blockIdx.x;
    int e = blockIdx.y * 256 + threadIdx.x;
    int l = t & (LL - 1);
    float acc = cb[e];
    #pragma unroll
    for (int k = 0; k < KC; k++) {
        int ll = l - (KC - 1) + k;
        if (ll >= 0)
            acc = fmaf(xz[(size_t)(t - (KC - 1) + k) * (2 * DI) + e], cw[e * KC + k], acc);
    }
    float s = 1.f / (1.f + expf(-acc));
    xc[(size_t)t * DI + e] = acc * s;
}

// ---------------- selective scan + skip + gate ------------------------------
// grid (4, B): blockIdx.x selects 128-channel chunk, blockIdx.y = batch
__global__ void scan_kernel(const float* __restrict__ dbc,
                            const float* __restrict__ dtf,
                            const float* __restrict__ xc,
                            const float* __restrict__ xz,
                            const float* __restrict__ A_log,
                            const float* __restrict__ Dskip,
                            float* __restrict__ y)
{
    int b = blockIdx.y;
    int tid = threadIdx.x;
    int e = blockIdx.x * 128 + tid;
    __shared__ float sB[2][NS], sC[2][NS];

    float A[NS], h[NS];
    #pragma unroll
    for (int n = 0; n < NS; n++) {
        A[n] = -expf(A_log[e * NS + n]);
        h[n] = 0.f;
    }
    float Ds = Dskip[e];

    {   // preload l=0
        int t0 = b * LL;
        if (tid < NS)            sB[0][tid]      = dbc[(size_t)t0 * 48 + RR + tid];
        else if (tid < 2 * NS)   sC[0][tid - NS] = dbc[(size_t)t0 * 48 + RR + NS + (tid - NS)];
    }
    __syncthreads();

    for (int l = 0; l < LL; l++) {
        int p = l & 1;
        if (l + 1 < LL) {
            int t1 = b * LL + l + 1;
            if (tid < NS)          sB[p ^ 1][tid]      = dbc[(size_t)t1 * 48 + RR + tid];
            else if (tid < 2 * NS) sC[p ^ 1][tid - NS] = dbc[(size_t)t1 * 48 + RR + NS + (tid - NS)];
        }
        int t = b * LL + l;
        float dtv = dtf[(size_t)t * DI + e];
        float xv  = xc[(size_t)t * DI + e];
        float du  = dtv * xv;
        float acc = 0.f;
        #pragma unroll
        for (int n = 0; n < NS; n++) {
            float dA = expf(dtv * A[n]);
            h[n] = fmaf(h[n], dA, du * sB[p][n]);
            acc = fmaf(h[n], sC[p][n], acc);
        }
        float zv = xz[(size_t)t * (2 * DI) + DI + e];
        float sig = 1.f / (1.f + expf(-zv));
        y[(size_t)t * DI + e] = (acc + xv * Ds) * (zv * sig);
        __syncthreads();
    }
}

// ---------------- host side --------------------------------------------------
extern "C" void kernel_launch(void* const* d_in, const int* in_sizes, int n_in,
                              void* d_out, int out_size)
{
    // metadata order = reference() signature order
    const int*   tok    = (const int*)  d_in[0];
    const float* emb    = (const float*)d_in[1];
    const float* ln_w   = (const float*)d_in[2];
    const float* ln_b   = (const float*)d_in[3];
    const float* in_w   = (const float*)d_in[4];   // (NL, 2DI, D)
    const float* conv_w = (const float*)d_in[5];   // (NL, DI, K)
    const float* conv_b = (const float*)d_in[6];   // (NL, DI)
    const float* xp_w   = (const float*)d_in[7];   // (NL, 48, DI)
    const float* dt_w   = (const float*)d_in[8];   // (NL, DI, R)
    const float* dt_b   = (const float*)d_in[9];   // (NL, DI)
    const float* A_log  = (const float*)d_in[10];  // (NL, DI, N)
    const float* Dskip  = (const float*)d_in[11];  // (NL, DI)
    const float* out_w  = (const float*)d_in[12];  // (NL, D, DI)
    const float* W1     = (const float*)d_in[13];  // (FF, D)
    const float* b1     = (const float*)d_in[14];
    const float* W2     = (const float*)d_in[15];  // (V, FF)
    const float* b2     = (const float*)d_in[16];
    float* out = (float*)d_out;

    float *px, *ph, *pxz, *pxc, *pdbc, *pdt, *py, *ph1;
    cudaGetSymbolAddress((void**)&px,   g_x);
    cudaGetSymbolAddress((void**)&ph,   g_h);
    cudaGetSymbolAddress((void**)&pxz,  g_xz);
    cudaGetSymbolAddress((void**)&pxc,  g_xc);
    cudaGetSymbolAddress((void**)&pdbc, g_dbc);
    cudaGetSymbolAddress((void**)&pdt,  g_dt);
    cudaGetSymbolAddress((void**)&py,   g_y);
    cudaGetSymbolAddress((void**)&ph1,  g_h1);

    embed_kernel<<<TT, D>>>(tok, emb, px);

    for (int l = 0; l < NL; l++) {
        const float* lw  = ln_w   + (size_t)l * D;
        const float* lb  = ln_b   + (size_t)l * D;
        const float* iw  = in_w   + (size_t)l * 2 * DI * D;
        const float* cw  = conv_w + (size_t)l * DI * KC;
        const float* cb  = conv_b + (size_t)l * DI;
        const float* xw  = xp_w   + (size_t)l * 48 * DI;
        const float* dw  = dt_w   + (size_t)l * DI * RR;
        const float* db  = dt_b   + (size_t)l * DI;
        const float* al  = A_log  + (size_t)l * DI * NS;
        const float* ds  = Dskip  + (size_t)l * DI;
        const float* ow  = out_w  + (size_t)l * D * DI;

        ln_kernel<<<TT, D>>>(px, lw, lb, ph);

        // xz = LN(x) @ in_w^T   (8192 x 1024 x 256)
        gemm_nt<0><<<dim3((2 * DI) / BN, TT / BM), 256>>>(
            ph, D, iw, D, pxz, 2 * DI, nullptr, nullptr, TT, 2 * DI, D);

        // conv + silu -> xc
        conv_kernel<<<dim3(TT, 2), 256>>>(pxz, cw, cb, pxc);

        // dbc = xc @ xp_w^T   (8192 x 48 x 512)
        gemm_nt<0><<<dim3(1, TT / BM), 256>>>(
            pxc, DI, xw, DI, pdbc, 48, nullptr, nullptr, TT, 48, DI);

        // dt = softplus(dbc[:, :16] @ dt_w^T + dt_b)   (8192 x 512 x 16)
        gemm_nt<4><<<dim3(DI / BN, TT / BM), 256>>>(
            pdbc, 48, dw, RR, pdt, DI, db, nullptr, TT, DI, RR);

        // selective scan + D-skip + SiLU(z) gate
        scan_kernel<<<dim3(4, BB), 128>>>(pdbc, pdt, pxc, pxz, al, ds, py);

        // x += y @ out_w^T   (8192 x 256 x 512), residual fused
        gemm_nt<3><<<dim3(D / BN, TT / BM), 256>>>(
            py, DI, ow, DI, px, D, nullptr, px, TT, D, DI);
    }

    // head: h1 = relu(x @ W1^T + b1)
    gemm_nt<1><<<dim3(FF / BN, TT / BM), 256>>>(
        px, D, W1, D, ph1, FF, b1, nullptr, TT, FF, D);
    // logits = h1 @ W2^T + b2
    gemm_nt<2><<<dim3(VV / BN, TT / BM), 256>>>(
        ph1, FF, W2, FF, out, VV, b2, nullptr, TT, VV, FF);
}